// round 13
// baseline (speedup 1.0000x reference)
#include <cuda_runtime.h>
#include <math.h>

#define Bb 4
#define Ss 2048
#define Dd 1024
#define Hh 16
#define BHn (Bb*Hh)      // 64
#define BSn (Bb*Ss)      // 8192
#define QKSCALE 0.3535533905932738f  // 64^-0.25

// swizzle: permutes float4 groups within a 64-float row, function of row index k
#define ZS(k) ((((k) >> 2) & 7) << 2)

typedef unsigned long long u64t;

// ---------------- packed f32x2 helpers ----------------
__device__ __forceinline__ u64t pk2(float x, float y) {
    u64t r; asm("mov.b64 %0, {%1,%2};" : "=l"(r) : "f"(x), "f"(y)); return r;
}
__device__ __forceinline__ u64t pkdup(float x) {
    u64t r; asm("mov.b64 %0, {%1,%1};" : "=l"(r) : "f"(x)); return r;
}
__device__ __forceinline__ void fma2(u64t& d, u64t a, u64t b) {
    asm("fma.rn.f32x2 %0, %1, %2, %0;" : "+l"(d) : "l"(a), "l"(b));
}
__device__ __forceinline__ float2 upk(u64t v) {
    float2 r; asm("mov.b64 {%0,%1}, %2;" : "=f"(r.x), "=f"(r.y) : "l"(v)); return r;
}

// ---------------- scratch (static device globals; no allocation) ----------------
__device__ float g_q[(size_t)BHn*Ss*64];
__device__ float g_k[(size_t)BHn*Ss*64];
__device__ float g_v[(size_t)BHn*Ss*64];
__device__ float g_attn[(size_t)BSn*Dd];   // pre-Wo activations [b,s,d]
__device__ float g_cos[Ss*32];
__device__ float g_sin[Ss*32];

// ---------------- RoPE table ----------------
__global__ void rope_table_kernel(const float* __restrict__ inv_freq,
                                  const float* __restrict__ rbias) {
    int idx = blockIdx.x * blockDim.x + threadIdx.x;
    if (idx >= Ss * 32) return;
    int t = idx >> 5, j = idx & 31;
    float ang = (float)t * inv_freq[j] + rbias[t * 32 + j];
    float s, c;
    sincosf(ang, &s, &c);
    g_cos[idx] = c;
    g_sin[idx] = s;
}

// ---------------- fused QKV projection: pipelined 2-stage GEMM, f32x2 core ----------------
// grid: (8, 64, 3), block 256
__global__ __launch_bounds__(256, 2) void qkv_kernel(
    const float* __restrict__ x,
    const float* __restrict__ Wq, const float* __restrict__ bq,
    const float* __restrict__ Wk,
    const float* __restrict__ Wv, const float* __restrict__ bv)
{
    __shared__ float As[2][16][128];
    __shared__ float Bs[2][16][128];
    const int z = blockIdx.z;
    const float* W    = (z == 0) ? Wq : (z == 1) ? Wk : Wv;
    const float* bias = (z == 0) ? bq : (z == 2) ? bv : nullptr;
    const int m0 = blockIdx.y * 128, n0 = blockIdx.x * 128;
    const int t = threadIdx.x;
    const int lr = t >> 2, lc = (t & 3) << 2;
    const int ty = t >> 4, tx = t & 15;

    const float* Ar0 = x + (size_t)(m0 + lr) * 1024 + lc;
    const float* Ar1 = Ar0 + (size_t)64 * 1024;
    const float* Br0 = W + (size_t)(n0 + lr) * 1024 + lc;
    const float* Br1 = Br0 + (size_t)64 * 1024;

    u64t acc2[8][4];
#pragma unroll
    for (int i = 0; i < 8; i++)
#pragma unroll
        for (int jp = 0; jp < 4; jp++) acc2[i][jp] = 0ull;

    float4 pa0 = *(const float4*)Ar0;
    float4 pa1 = *(const float4*)Ar1;
    float4 pb0 = *(const float4*)Br0;
    float4 pb1 = *(const float4*)Br1;

    for (int tile = 0; tile < 64; tile++) {
        const int cur = tile & 1;
        As[cur][lc + 0][lr] = pa0.x; As[cur][lc + 1][lr] = pa0.y;
        As[cur][lc + 2][lr] = pa0.z; As[cur][lc + 3][lr] = pa0.w;
        As[cur][lc + 0][lr + 64] = pa1.x; As[cur][lc + 1][lr + 64] = pa1.y;
        As[cur][lc + 2][lr + 64] = pa1.z; As[cur][lc + 3][lr + 64] = pa1.w;
        Bs[cur][lc + 0][lr] = pb0.x; Bs[cur][lc + 1][lr] = pb0.y;
        Bs[cur][lc + 2][lr] = pb0.z; Bs[cur][lc + 3][lr] = pb0.w;
        Bs[cur][lc + 0][lr + 64] = pb1.x; Bs[cur][lc + 1][lr + 64] = pb1.y;
        Bs[cur][lc + 2][lr + 64] = pb1.z; Bs[cur][lc + 3][lr + 64] = pb1.w;
        __syncthreads();
        if (tile < 63) {
            int off = (tile + 1) * 16;
            pa0 = *(const float4*)(Ar0 + off);
            pa1 = *(const float4*)(Ar1 + off);
            pb0 = *(const float4*)(Br0 + off);
            pb1 = *(const float4*)(Br1 + off);
        }
#pragma unroll
        for (int k = 0; k < 16; k++) {
            float a[8];
            float4 bl0 = *(const float4*)&Bs[cur][k][tx * 4];
            float4 bl1 = *(const float4*)&Bs[cur][k][tx * 4 + 64];
            *(float4*)(a)     = *(const float4*)&As[cur][k][ty * 4];
            *(float4*)(a + 4) = *(const float4*)&As[cur][k][ty * 4 + 64];
            u64t b2[4];
            b2[0] = pk2(bl0.x, bl0.y); b2[1] = pk2(bl0.z, bl0.w);
            b2[2] = pk2(bl1.x, bl1.y); b2[3] = pk2(bl1.z, bl1.w);
#pragma unroll
            for (int i = 0; i < 8; i++) {
                u64t ai = pkdup(a[i]);
                fma2(acc2[i][0], ai, b2[0]);
                fma2(acc2[i][1], ai, b2[1]);
                fma2(acc2[i][2], ai, b2[2]);
                fma2(acc2[i][3], ai, b2[3]);
            }
        }
    }

    // epilogue: bias, RoPE, scale; float4 stores (4-aligned hd groups never cross a head)
#pragma unroll
    for (int i = 0; i < 8; i++) {
        int m = m0 + ty * 4 + (i & 3) + ((i >> 2) << 6);
        int s = m & (Ss - 1);
        int bidx = m >> 11;
#pragma unroll
        for (int jg = 0; jg < 2; jg++) {
            int n = n0 + tx * 4 + (jg << 6);       // 4-aligned, head-uniform group
            float2 u0 = upk(acc2[i][jg * 2 + 0]);
            float2 u1 = upk(acc2[i][jg * 2 + 1]);
            float y0 = u0.x, y1 = u0.y, y2 = u1.x, y3 = u1.y;
            if (bias != nullptr) {
                float4 bv4 = *(const float4*)(bias + n);
                y0 += bv4.x; y1 += bv4.y; y2 += bv4.z; y3 += bv4.w;
            }
            int h = n >> 6, hd = n & 63;
            size_t o = (((size_t)(bidx * Hh + h) * Ss + s) << 6) + hd;
            if (z == 2) {
                *(float4*)(&g_v[o]) = make_float4(y0, y1, y2, y3);
            } else {
                int jr = hd >> 1;
                float2 cs0 = *(const float2*)(&g_cos[s * 32 + jr]);
                float2 sn0 = *(const float2*)(&g_sin[s * 32 + jr]);
                float r0 = (y0 * cs0.x - y1 * sn0.x) * QKSCALE;
                float i0 = (y0 * sn0.x + y1 * cs0.x) * QKSCALE;
                float r1 = (y2 * cs0.y - y3 * sn0.y) * QKSCALE;
                float i1 = (y2 * sn0.y + y3 * cs0.y) * QKSCALE;
                float* dst = (z == 0) ? g_q : g_k;
                *(float4*)(&dst[o]) = make_float4(r0, i0, r1, i1);
            }
        }
    }
}

// ---------------- fused attention: all buffers double, ONE sync per chunk ----------------
// dynamic smem 112KB: Qs[4096] | Ks[2][4096] | Vs[2][4096] | Ps[2][4096]
// grid: 2048 (64 bh x 32 q-tiles of 64 rows), block 256 (ty x tx 16x16; 4x4 per thread)
// Race discipline: every RAW/WAR pair on a buffer is separated by exactly one barrier:
//   K[b] stash (pre-sync, iter c) vs S reads (post-sync iter c+1 / pre-sync iter c-1)
//   V[b] stash moved AFTER the sync (iter c) vs PV reads (post-sync iter c+1 / pre-sync... c-1 reads end before sync_c)
//   P[b] write (pre-sync, iter c) vs PV reads (post-sync iter c, and iter c-2 reads end a barrier earlier)
__global__ __launch_bounds__(256, 2) void attn_fused_kernel(const float* __restrict__ mask,
                                                            float* __restrict__ qk_out)
{
    extern __shared__ float sm[];
    float* Qs = sm;             // [hd][qrow^z]
    float* Ks = sm + 4096;      // 2 bufs: K^T [hd][kv^z]
    float* Vs = sm + 12288;     // 2 bufs: [kv][hd^z]
    float* Ps = sm + 20480;     // 2 bufs: P^T [kv][qrow^z]

    const int blk = blockIdx.x;
    const int bh = blk >> 5;
    const int m0 = (blk & 31) << 6;
    const float* Qg = g_q + (size_t)bh * Ss * 64;
    const float* Kg = g_k + (size_t)bh * Ss * 64;
    const float* Vg = g_v + (size_t)bh * Ss * 64;
    const int t = threadIdx.x;
    const int ty = t >> 4, tx = t & 15;
    const int lrow = t >> 4;
    const int lc4 = t & 15;
    const int zl = (lc4 & 7) << 2;     // == ZS(4*lc4+u) for u<4

    // prolog: load Q tile (transposed+swizzled); stash K/V chunk0 to buf0; prefetch chunk1
    float4 kpre[4], vpre[4];
#pragma unroll
    for (int it = 0; it < 4; it++) {
        int row = lrow + it * 16;
        float4 v = *(const float4*)(Qg + (size_t)(m0 + row) * 64 + lc4 * 4);
        int pr = row ^ zl;
        Qs[(lc4 * 4 + 0) * 64 + pr] = v.x;
        Qs[(lc4 * 4 + 1) * 64 + pr] = v.y;
        Qs[(lc4 * 4 + 2) * 64 + pr] = v.z;
        Qs[(lc4 * 4 + 3) * 64 + pr] = v.w;
        kpre[it] = *(const float4*)(Kg + (size_t)row * 64 + lc4 * 4);
        vpre[it] = *(const float4*)(Vg + (size_t)row * 64 + lc4 * 4);
    }
#pragma unroll
    for (int it = 0; it < 4; it++) {
        int row = lrow + it * 16;
        int pr = row ^ zl;
        Ks[(lc4 * 4 + 0) * 64 + pr] = kpre[it].x;
        Ks[(lc4 * 4 + 1) * 64 + pr] = kpre[it].y;
        Ks[(lc4 * 4 + 2) * 64 + pr] = kpre[it].z;
        Ks[(lc4 * 4 + 3) * 64 + pr] = kpre[it].w;
        *(float4*)&Vs[row * 64 + ((lc4 * 4) ^ ZS(row))] = vpre[it];
        int row1 = 64 + row;
        kpre[it] = *(const float4*)(Kg + (size_t)row1 * 64 + lc4 * 4);
        vpre[it] = *(const float4*)(Vg + (size_t)row1 * 64 + lc4 * 4);
    }
    __syncthreads();

    u64t o2[4][2];
    float s_run[4];
#pragma unroll
    for (int i = 0; i < 4; i++) {
        s_run[i] = 0.f;
        o2[i][0] = 0ull; o2[i][1] = 0ull;
    }

    for (int c = 0; c < 32; c++) {
        const int kc = c << 6;
        const int cur = c & 1;
        const float* Kb = Ks + cur * 4096;
        const float* Vb = Vs + cur * 4096;
        float* Pb = Ps + cur * 4096;
        float* Kn = Ks + (cur ^ 1) * 4096;
        float* Vn = Vs + (cur ^ 1) * 4096;

        // mask rows for this chunk (consumed after S-GEMM)
        float4 mpre[4];
#pragma unroll
        for (int i = 0; i < 4; i++)
            mpre[i] = *(const float4*)(mask + (size_t)(m0 + ty * 4 + i) * Ss + kc + tx * 4);

        // ---- S = Q K^T over hd=64 (f32x2) ----
        u64t s2[4][2];
#pragma unroll
        for (int i = 0; i < 4; i++) { s2[i][0] = 0ull; s2[i][1] = 0ull; }
#pragma unroll 8
        for (int k = 0; k < 64; k++) {
            int zk = ZS(k);
            float4 a = *(const float4*)&Qs[k * 64 + ((ty * 4) ^ zk)];
            float4 b = *(const float4*)&Kb[k * 64 + ((tx * 4) ^ zk)];
            u64t b0 = pk2(b.x, b.y), b1 = pk2(b.z, b.w);
            u64t a0 = pkdup(a.x), a1 = pkdup(a.y), a2 = pkdup(a.z), a3 = pkdup(a.w);
            fma2(s2[0][0], a0, b0); fma2(s2[0][1], a0, b1);
            fma2(s2[1][0], a1, b0); fma2(s2[1][1], a1, b1);
            fma2(s2[2][0], a2, b0); fma2(s2[2][1], a2, b1);
            fma2(s2[3][0], a3, b0); fma2(s2[3][1], a3, b1);
        }

        // ---- mask add, streaming store qk, exp; per-thread row-sum (reduced once at end) ----
        float p[4][4];
#pragma unroll
        for (int i = 0; i < 4; i++) {
            int m = m0 + ty * 4 + i;
            float2 u0 = upk(s2[i][0]);
            float2 u1 = upk(s2[i][1]);
            float v0 = u0.x + mpre[i].x, v1 = u0.y + mpre[i].y;
            float v2 = u1.x + mpre[i].z, v3 = u1.y + mpre[i].w;
            __stcs((float4*)(qk_out + ((size_t)bh * Ss + m) * Ss + kc + tx * 4),
                   make_float4(v0, v1, v2, v3));
            float p0 = __expf(v0), p1 = __expf(v1);
            float p2 = __expf(v2), p3 = __expf(v3);
            p[i][0] = p0; p[i][1] = p1; p[i][2] = p2; p[i][3] = p3;
            s_run[i] += (p0 + p1) + (p2 + p3);
        }

        // ---- write P^T into Pb (cur buffer) ----
        {
            int zp = (tx & 7) << 2;
#pragma unroll
            for (int j = 0; j < 4; j++) {
                float* dst = &Pb[(tx * 4 + j) * 64];
#pragma unroll
                for (int i = 0; i < 4; i++)
                    dst[(ty * 4 + i) ^ zp] = p[i][j];
            }
        }

        // ---- stash K(c+1) into Kn; prefetch K(c+2) ----
        if (c < 31) {
#pragma unroll
            for (int it = 0; it < 4; it++) {
                int row = lrow + it * 16;
                int pr = row ^ zl;
                Kn[(lc4 * 4 + 0) * 64 + pr] = kpre[it].x;
                Kn[(lc4 * 4 + 1) * 64 + pr] = kpre[it].y;
                Kn[(lc4 * 4 + 2) * 64 + pr] = kpre[it].z;
                Kn[(lc4 * 4 + 3) * 64 + pr] = kpre[it].w;
            }
            if (c < 30) {
#pragma unroll
                for (int it = 0; it < 4; it++) {
                    int row = kc + 128 + lrow + it * 16;
                    kpre[it] = *(const float4*)(Kg + (size_t)row * 64 + lc4 * 4);
                }
            }
        }

        __syncthreads();   // the ONE barrier per chunk

        // ---- O += P V over kv=64 (f32x2) ----
#pragma unroll 8
        for (int k = 0; k < 64; k++) {
            int zk = ZS(k);
            float4 a = *(const float4*)&Pb[k * 64 + ((ty * 4) ^ zk)];
            float4 b = *(const float4*)&Vb[k * 64 + ((tx * 4) ^ zk)];
            u64t b0 = pk2(b.x, b.y), b1 = pk2(b.z, b.w);
            u64t a0 = pkdup(a.x), a1 = pkdup(a.y), a2 = pkdup(a.z), a3 = pkdup(a.w);
            fma2(o2[0][0], a0, b0); fma2(o2[0][1], a0, b1);
            fma2(o2[1][0], a1, b0); fma2(o2[1][1], a1, b1);
            fma2(o2[2][0], a2, b0); fma2(o2[2][1], a2, b1);
            fma2(o2[3][0], a3, b0); fma2(o2[3][1], a3, b1);
        }

        // ---- stash V(c+1) into Vn (post-sync interval); prefetch V(c+2) ----
        if (c < 31) {
#pragma unroll
            for (int it = 0; it < 4; it++) {
                int row = lrow + it * 16;
                *(float4*)&Vn[row * 64 + ((lc4 * 4) ^ ZS(row))] = vpre[it];
            }
            if (c < 30) {
#pragma unroll
                for (int it = 0; it < 4; it++) {
                    int row = kc + 128 + lrow + it * 16;
                    vpre[it] = *(const float4*)(Vg + (size_t)row * 64 + lc4 * 4);
                }
            }
        }
    }

    // ---- final row-sum reduction (once), normalize, write pre-Wo activations ----
#pragma unroll
    for (int i = 0; i < 4; i++) {
        s_run[i] += __shfl_xor_sync(0xffffffffu, s_run[i], 1);
        s_run[i] += __shfl_xor_sync(0xffffffffu, s_run[i], 2);
        s_run[i] += __shfl_xor_sync(0xffffffffu, s_run[i], 4);
        s_run[i] += __shfl_xor_sync(0xffffffffu, s_run[i], 8);
    }
    const int b_ = bh >> 4, h = bh & 15;
#pragma unroll
    for (int i = 0; i < 4; i++) {
        float inv = 1.0f / s_run[i];
        int m = m0 + ty * 4 + i;
        float2 u0 = upk(o2[i][0]);
        float2 u1 = upk(o2[i][1]);
        *(float4*)(g_attn + (size_t)(b_ * Ss + m) * 1024 + h * 64 + tx * 4) =
            make_float4(u0.x * inv, u0.y * inv, u1.x * inv, u1.y * inv);
    }
}

// ---------------- output projection: pipelined 2-stage GEMM, f32x2 core ----------------
// grid: (8, 64), block 256
__global__ __launch_bounds__(256, 2) void oproj_kernel(const float* __restrict__ Wo,
                                                       const float* __restrict__ bo,
                                                       float* __restrict__ out)
{
    __shared__ float As[2][16][128];
    __shared__ float Bs[2][16][128];
    const int m0 = blockIdx.y * 128, n0 = blockIdx.x * 128;
    const int t = threadIdx.x;
    const int lr = t >> 2, lc = (t & 3) << 2;
    const int ty = t >> 4, tx = t & 15;

    const float* Ar0 = g_attn + (size_t)(m0 + lr) * 1024 + lc;
    const float* Ar1 = Ar0 + (size_t)64 * 1024;
    const float* Br0 = Wo + (size_t)(n0 + lr) * 1024 + lc;
    const float* Br1 = Br0 + (size_t)64 * 1024;

    u64t acc2[8][4];
#pragma unroll
    for (int i = 0; i < 8; i++)
#pragma unroll
        for (int jp = 0; jp < 4; jp++) acc2[i][jp] = 0ull;

    float4 pa0 = *(const float4*)Ar0;
    float4 pa1 = *(const float4*)Ar1;
    float4 pb0 = *(const float4*)Br0;
    float4 pb1 = *(const float4*)Br1;

    for (int tile = 0; tile < 64; tile++) {
        const int cur = tile & 1;
        As[cur][lc + 0][lr] = pa0.x; As[cur][lc + 1][lr] = pa0.y;
        As[cur][lc + 2][lr] = pa0.z; As[cur][lc + 3][lr] = pa0.w;
        As[cur][lc + 0][lr + 64] = pa1.x; As[cur][lc + 1][lr + 64] = pa1.y;
        As[cur][lc + 2][lr + 64] = pa1.z; As[cur][lc + 3][lr + 64] = pa1.w;
        Bs[cur][lc + 0][lr] = pb0.x; Bs[cur][lc + 1][lr] = pb0.y;
        Bs[cur][lc + 2][lr] = pb0.z; Bs[cur][lc + 3][lr] = pb0.w;
        Bs[cur][lc + 0][lr + 64] = pb1.x; Bs[cur][lc + 1][lr + 64] = pb1.y;
        Bs[cur][lc + 2][lr + 64] = pb1.z; Bs[cur][lc + 3][lr + 64] = pb1.w;
        __syncthreads();
        if (tile < 63) {
            int off = (tile + 1) * 16;
            pa0 = *(const float4*)(Ar0 + off);
            pa1 = *(const float4*)(Ar1 + off);
            pb0 = *(const float4*)(Br0 + off);
            pb1 = *(const float4*)(Br1 + off);
        }
#pragma unroll
        for (int k = 0; k < 16; k++) {
            float a[8];
            float4 bl0 = *(const float4*)&Bs[cur][k][tx * 4];
            float4 bl1 = *(const float4*)&Bs[cur][k][tx * 4 + 64];
            *(float4*)(a)     = *(const float4*)&As[cur][k][ty * 4];
            *(float4*)(a + 4) = *(const float4*)&As[cur][k][ty * 4 + 64];
            u64t b2[4];
            b2[0] = pk2(bl0.x, bl0.y); b2[1] = pk2(bl0.z, bl0.w);
            b2[2] = pk2(bl1.x, bl1.y); b2[3] = pk2(bl1.z, bl1.w);
#pragma unroll
            for (int i = 0; i < 8; i++) {
                u64t ai = pkdup(a[i]);
                fma2(acc2[i][0], ai, b2[0]);
                fma2(acc2[i][1], ai, b2[1]);
                fma2(acc2[i][2], ai, b2[2]);
                fma2(acc2[i][3], ai, b2[3]);
            }
        }
    }

#pragma unroll
    for (int i = 0; i < 8; i++) {
        int m = m0 + ty * 4 + (i & 3) + ((i >> 2) << 6);
        float* orow = out + (size_t)m * 1024;
#pragma unroll
        for (int jg = 0; jg < 2; jg++) {
            int n = n0 + tx * 4 + jg * 64;
            float4 bv = *(const float4*)(bo + n);
            float2 u0 = upk(acc2[i][jg * 2 + 0]);
            float2 u1 = upk(acc2[i][jg * 2 + 1]);
            float4 ov;
            ov.x = u0.x + bv.x;
            ov.y = u0.y + bv.y;
            ov.z = u1.x + bv.z;
            ov.w = u1.y + bv.w;
            *(float4*)(orow + n) = ov;
        }
    }
}

// ---------------- launch ----------------
extern "C" void kernel_launch(void* const* d_in, const int* in_sizes, int n_in,
                              void* d_out, int out_size)
{
    const float* x        = (const float*)d_in[0];
    const float* Wq       = (const float*)d_in[1];
    const float* bq       = (const float*)d_in[2];
    const float* Wk       = (const float*)d_in[3];
    const float* Wv       = (const float*)d_in[4];
    const float* bv       = (const float*)d_in[5];
    const float* Wo       = (const float*)d_in[6];
    const float* bo       = (const float*)d_in[7];
    const float* inv_freq = (const float*)d_in[8];
    const float* rbias    = (const float*)d_in[9];
    const float* mask     = (const float*)d_in[10];

    float* out    = (float*)d_out;
    float* qk_out = out + (size_t)BSn * Dd;   // second output: (B,H,S,S)

    // raise dynamic smem limit for the attention kernel (idempotent; host-side, not captured)
    static int smem_set = 0;
    if (!smem_set) {
        cudaFuncSetAttribute(attn_fused_kernel,
                             cudaFuncAttributeMaxDynamicSharedMemorySize, 112 * 1024);
        smem_set = 1;
    }

    rope_table_kernel<<<(Ss * 32 + 255) / 256, 256>>>(inv_freq, rbias);

    dim3 gA(8, 64, 3);
    qkv_kernel<<<gA, 256>>>(x, Wq, bq, Wk, Wv, bv);

    attn_fused_kernel<<<2048, 256, 112 * 1024>>>(mask, qk_out);

    dim3 gD(8, 64);
    oproj_kernel<<<gD, 256>>>(Wo, bo, out);
}

// round 14
// speedup vs baseline: 1.0773x; 1.0773x over previous
#include <cuda_runtime.h>
#include <math.h>

#define Bb 4
#define Ss 2048
#define Dd 1024
#define Hh 16
#define BHn (Bb*Hh)      // 64
#define BSn (Bb*Ss)      // 8192
#define QKSCALE 0.3535533905932738f  // 64^-0.25

// swizzle: permutes float4 groups within a 64-float row, function of row index k
#define ZS(k) ((((k) >> 2) & 7) << 2)

typedef unsigned long long u64t;

// ---------------- packed f32x2 helpers ----------------
__device__ __forceinline__ u64t pk2(float x, float y) {
    u64t r; asm("mov.b64 %0, {%1,%2};" : "=l"(r) : "f"(x), "f"(y)); return r;
}
__device__ __forceinline__ u64t pkdup(float x) {
    u64t r; asm("mov.b64 %0, {%1,%1};" : "=l"(r) : "f"(x)); return r;
}
__device__ __forceinline__ void fma2(u64t& d, u64t a, u64t b) {
    asm("fma.rn.f32x2 %0, %1, %2, %0;" : "+l"(d) : "l"(a), "l"(b));
}
__device__ __forceinline__ float2 upk(u64t v) {
    float2 r; asm("mov.b64 {%0,%1}, %2;" : "=f"(r.x), "=f"(r.y) : "l"(v)); return r;
}

// ---------------- scratch (static device globals; no allocation) ----------------
__device__ float g_q[(size_t)BHn*Ss*64];
__device__ float g_k[(size_t)BHn*Ss*64];
__device__ float g_v[(size_t)BHn*Ss*64];
__device__ float g_attn[(size_t)BSn*Dd];   // pre-Wo activations [b,s,d]
__device__ float g_cos[Ss*32];
__device__ float g_sin[Ss*32];

// ---------------- RoPE table ----------------
__global__ void rope_table_kernel(const float* __restrict__ inv_freq,
                                  const float* __restrict__ rbias) {
    int idx = blockIdx.x * blockDim.x + threadIdx.x;
    if (idx >= Ss * 32) return;
    int t = idx >> 5, j = idx & 31;
    float ang = (float)t * inv_freq[j] + rbias[t * 32 + j];
    float s, c;
    sincosf(ang, &s, &c);
    g_cos[idx] = c;
    g_sin[idx] = s;
}

// ---------------- fused QKV projection: pipelined 2-stage GEMM, f32x2 core ----------------
// grid: (8, 64, 3), block 256
__global__ __launch_bounds__(256, 2) void qkv_kernel(
    const float* __restrict__ x,
    const float* __restrict__ Wq, const float* __restrict__ bq,
    const float* __restrict__ Wk,
    const float* __restrict__ Wv, const float* __restrict__ bv)
{
    __shared__ float As[2][16][128];
    __shared__ float Bs[2][16][128];
    const int z = blockIdx.z;
    const float* W    = (z == 0) ? Wq : (z == 1) ? Wk : Wv;
    const float* bias = (z == 0) ? bq : (z == 2) ? bv : nullptr;
    const int m0 = blockIdx.y * 128, n0 = blockIdx.x * 128;
    const int t = threadIdx.x;
    const int lr = t >> 2, lc = (t & 3) << 2;
    const int ty = t >> 4, tx = t & 15;

    const float* Ar0 = x + (size_t)(m0 + lr) * 1024 + lc;
    const float* Ar1 = Ar0 + (size_t)64 * 1024;
    const float* Br0 = W + (size_t)(n0 + lr) * 1024 + lc;
    const float* Br1 = Br0 + (size_t)64 * 1024;

    u64t acc2[8][4];
#pragma unroll
    for (int i = 0; i < 8; i++)
#pragma unroll
        for (int jp = 0; jp < 4; jp++) acc2[i][jp] = 0ull;

    float4 pa0 = *(const float4*)Ar0;
    float4 pa1 = *(const float4*)Ar1;
    float4 pb0 = *(const float4*)Br0;
    float4 pb1 = *(const float4*)Br1;

    for (int tile = 0; tile < 64; tile++) {
        const int cur = tile & 1;
        As[cur][lc + 0][lr] = pa0.x; As[cur][lc + 1][lr] = pa0.y;
        As[cur][lc + 2][lr] = pa0.z; As[cur][lc + 3][lr] = pa0.w;
        As[cur][lc + 0][lr + 64] = pa1.x; As[cur][lc + 1][lr + 64] = pa1.y;
        As[cur][lc + 2][lr + 64] = pa1.z; As[cur][lc + 3][lr + 64] = pa1.w;
        Bs[cur][lc + 0][lr] = pb0.x; Bs[cur][lc + 1][lr] = pb0.y;
        Bs[cur][lc + 2][lr] = pb0.z; Bs[cur][lc + 3][lr] = pb0.w;
        Bs[cur][lc + 0][lr + 64] = pb1.x; Bs[cur][lc + 1][lr + 64] = pb1.y;
        Bs[cur][lc + 2][lr + 64] = pb1.z; Bs[cur][lc + 3][lr + 64] = pb1.w;
        __syncthreads();
        if (tile < 63) {
            int off = (tile + 1) * 16;
            pa0 = *(const float4*)(Ar0 + off);
            pa1 = *(const float4*)(Ar1 + off);
            pb0 = *(const float4*)(Br0 + off);
            pb1 = *(const float4*)(Br1 + off);
        }
#pragma unroll
        for (int k = 0; k < 16; k++) {
            float a[8];
            float4 bl0 = *(const float4*)&Bs[cur][k][tx * 4];
            float4 bl1 = *(const float4*)&Bs[cur][k][tx * 4 + 64];
            *(float4*)(a)     = *(const float4*)&As[cur][k][ty * 4];
            *(float4*)(a + 4) = *(const float4*)&As[cur][k][ty * 4 + 64];
            u64t b2[4];
            b2[0] = pk2(bl0.x, bl0.y); b2[1] = pk2(bl0.z, bl0.w);
            b2[2] = pk2(bl1.x, bl1.y); b2[3] = pk2(bl1.z, bl1.w);
#pragma unroll
            for (int i = 0; i < 8; i++) {
                u64t ai = pkdup(a[i]);
                fma2(acc2[i][0], ai, b2[0]);
                fma2(acc2[i][1], ai, b2[1]);
                fma2(acc2[i][2], ai, b2[2]);
                fma2(acc2[i][3], ai, b2[3]);
            }
        }
    }

    // epilogue: bias, RoPE, scale; float4 stores (4-aligned hd groups never cross a head)
#pragma unroll
    for (int i = 0; i < 8; i++) {
        int m = m0 + ty * 4 + (i & 3) + ((i >> 2) << 6);
        int s = m & (Ss - 1);
        int bidx = m >> 11;
#pragma unroll
        for (int jg = 0; jg < 2; jg++) {
            int n = n0 + tx * 4 + (jg << 6);       // 4-aligned, head-uniform group
            float2 u0 = upk(acc2[i][jg * 2 + 0]);
            float2 u1 = upk(acc2[i][jg * 2 + 1]);
            float y0 = u0.x, y1 = u0.y, y2 = u1.x, y3 = u1.y;
            if (bias != nullptr) {
                float4 bv4 = *(const float4*)(bias + n);
                y0 += bv4.x; y1 += bv4.y; y2 += bv4.z; y3 += bv4.w;
            }
            int h = n >> 6, hd = n & 63;
            size_t o = (((size_t)(bidx * Hh + h) * Ss + s) << 6) + hd;
            if (z == 2) {
                *(float4*)(&g_v[o]) = make_float4(y0, y1, y2, y3);
            } else {
                int jr = hd >> 1;
                float2 cs0 = *(const float2*)(&g_cos[s * 32 + jr]);
                float2 sn0 = *(const float2*)(&g_sin[s * 32 + jr]);
                float r0 = (y0 * cs0.x - y1 * sn0.x) * QKSCALE;
                float i0 = (y0 * sn0.x + y1 * cs0.x) * QKSCALE;
                float r1 = (y2 * cs0.y - y3 * sn0.y) * QKSCALE;
                float i1 = (y2 * sn0.y + y3 * cs0.y) * QKSCALE;
                float* dst = (z == 0) ? g_q : g_k;
                *(float4*)(&dst[o]) = make_float4(r0, i0, r1, i1);
            }
        }
    }
}

// ---------------- fused attention: 128 threads, 8x4 thread tile, R12 2-sync schedule ----------------
// dynamic smem 96KB: Qs[4096] | Ks[2][4096] | Vs[2][4096] | Ps[4096]
// grid: 2048 (64 bh x 32 q-tiles of 64 rows), block 128 (ty 0-7 x tx 0-15; 8 rows x 4 cols per thread)
__global__ __launch_bounds__(128, 2) void attn_fused_kernel(const float* __restrict__ mask,
                                                            float* __restrict__ qk_out)
{
    extern __shared__ float sm[];
    float* Qs = sm;             // [hd][qrow^z]
    float* Ks = sm + 4096;      // 2 bufs: K^T [hd][kv^z]
    float* Vs = sm + 12288;     // 2 bufs: [kv][hd^z]
    float* Ps = sm + 20480;     // P^T [kv][qrow^z]

    const int blk = blockIdx.x;
    const int bh = blk >> 5;
    const int m0 = (blk & 31) << 6;
    const float* Qg = g_q + (size_t)bh * Ss * 64;
    const float* Kg = g_k + (size_t)bh * Ss * 64;
    const float* Vg = g_v + (size_t)bh * Ss * 64;
    const int t = threadIdx.x;
    const int ty = t >> 4, tx = t & 15;      // ty 0..7, tx 0..15
    const int lrow = t >> 4;                 // loader rows: lrow + it*8, it 0..7
    const int lc4 = t & 15;
    const int zl = (lc4 & 7) << 2;           // == ZS(4*lc4+u) for u<4

    // prolog: load Q tile (transposed+swizzled, 8 its); stash K/V chunk0; prefetch chunk1
    float4 kpre[8], vpre[8];
#pragma unroll
    for (int it = 0; it < 8; it++) {
        int row = lrow + it * 8;
        float4 v = *(const float4*)(Qg + (size_t)(m0 + row) * 64 + lc4 * 4);
        int pr = row ^ zl;
        Qs[(lc4 * 4 + 0) * 64 + pr] = v.x;
        Qs[(lc4 * 4 + 1) * 64 + pr] = v.y;
        Qs[(lc4 * 4 + 2) * 64 + pr] = v.z;
        Qs[(lc4 * 4 + 3) * 64 + pr] = v.w;
        kpre[it] = *(const float4*)(Kg + (size_t)row * 64 + lc4 * 4);
        vpre[it] = *(const float4*)(Vg + (size_t)row * 64 + lc4 * 4);
    }
#pragma unroll
    for (int it = 0; it < 8; it++) {
        int row = lrow + it * 8;
        int pr = row ^ zl;
        Ks[(lc4 * 4 + 0) * 64 + pr] = kpre[it].x;
        Ks[(lc4 * 4 + 1) * 64 + pr] = kpre[it].y;
        Ks[(lc4 * 4 + 2) * 64 + pr] = kpre[it].z;
        Ks[(lc4 * 4 + 3) * 64 + pr] = kpre[it].w;
        *(float4*)&Vs[row * 64 + ((lc4 * 4) ^ ZS(row))] = vpre[it];
        int row1 = 64 + row;
        kpre[it] = *(const float4*)(Kg + (size_t)row1 * 64 + lc4 * 4);
        vpre[it] = *(const float4*)(Vg + (size_t)row1 * 64 + lc4 * 4);
    }
    __syncthreads();

    u64t o2[8][2];
    float s_run[8];
#pragma unroll
    for (int i = 0; i < 8; i++) {
        s_run[i] = 0.f;
        o2[i][0] = 0ull; o2[i][1] = 0ull;
    }

    for (int c = 0; c < 32; c++) {
        const int kc = c << 6;
        const int cur = c & 1;
        const float* Kb = Ks + cur * 4096;
        const float* Vb = Vs + cur * 4096;
        float* Kn = Ks + (cur ^ 1) * 4096;
        float* Vn = Vs + (cur ^ 1) * 4096;

        // mask rows for this chunk (consumed after S-GEMM)
        float4 mpre[8];
#pragma unroll
        for (int i = 0; i < 8; i++)
            mpre[i] = *(const float4*)(mask + (size_t)(m0 + ty * 8 + i) * Ss + kc + tx * 4);

        // ---- S = Q K^T over hd=64 (f32x2), 8 rows x 4 cols per thread ----
        u64t s2[8][2];
#pragma unroll
        for (int i = 0; i < 8; i++) { s2[i][0] = 0ull; s2[i][1] = 0ull; }
#pragma unroll 8
        for (int k = 0; k < 64; k++) {
            int zk = ZS(k);
            float4 a0 = *(const float4*)&Qs[k * 64 + ((ty * 8) ^ zk)];
            float4 a1 = *(const float4*)&Qs[k * 64 + ((ty * 8 + 4) ^ zk)];
            float4 b  = *(const float4*)&Kb[k * 64 + ((tx * 4) ^ zk)];
            u64t b0 = pk2(b.x, b.y), b1 = pk2(b.z, b.w);
            u64t d0 = pkdup(a0.x), d1 = pkdup(a0.y), d2 = pkdup(a0.z), d3 = pkdup(a0.w);
            u64t d4 = pkdup(a1.x), d5 = pkdup(a1.y), d6 = pkdup(a1.z), d7 = pkdup(a1.w);
            fma2(s2[0][0], d0, b0); fma2(s2[0][1], d0, b1);
            fma2(s2[1][0], d1, b0); fma2(s2[1][1], d1, b1);
            fma2(s2[2][0], d2, b0); fma2(s2[2][1], d2, b1);
            fma2(s2[3][0], d3, b0); fma2(s2[3][1], d3, b1);
            fma2(s2[4][0], d4, b0); fma2(s2[4][1], d4, b1);
            fma2(s2[5][0], d5, b0); fma2(s2[5][1], d5, b1);
            fma2(s2[6][0], d6, b0); fma2(s2[6][1], d6, b1);
            fma2(s2[7][0], d7, b0); fma2(s2[7][1], d7, b1);
        }

        // ---- mask add, store qk, exp; per-thread row-sum (reduced once at end) ----
        float p[8][4];
#pragma unroll
        for (int i = 0; i < 8; i++) {
            int m = m0 + ty * 8 + i;
            float2 u0 = upk(s2[i][0]);
            float2 u1 = upk(s2[i][1]);
            float v0 = u0.x + mpre[i].x, v1 = u0.y + mpre[i].y;
            float v2 = u1.x + mpre[i].z, v3 = u1.y + mpre[i].w;
            *(float4*)(qk_out + ((size_t)bh * Ss + m) * Ss + kc + tx * 4) =
                make_float4(v0, v1, v2, v3);
            float p0 = __expf(v0), p1 = __expf(v1);
            float p2 = __expf(v2), p3 = __expf(v3);
            p[i][0] = p0; p[i][1] = p1; p[i][2] = p2; p[i][3] = p3;
            s_run[i] += (p0 + p1) + (p2 + p3);
        }

        // ---- write P^T into Ps ----
        {
            int zp = (tx & 7) << 2;
#pragma unroll
            for (int j = 0; j < 4; j++) {
                float* dst = &Ps[(tx * 4 + j) * 64];
#pragma unroll
                for (int i = 0; i < 8; i++)
                    dst[(ty * 8 + i) ^ zp] = p[i][j];
            }
        }

        // ---- stash K/V(c+1); prefetch K/V(c+2) ----
        if (c < 31) {
#pragma unroll
            for (int it = 0; it < 8; it++) {
                int row = lrow + it * 8;
                int pr = row ^ zl;
                Kn[(lc4 * 4 + 0) * 64 + pr] = kpre[it].x;
                Kn[(lc4 * 4 + 1) * 64 + pr] = kpre[it].y;
                Kn[(lc4 * 4 + 2) * 64 + pr] = kpre[it].z;
                Kn[(lc4 * 4 + 3) * 64 + pr] = kpre[it].w;
                *(float4*)&Vn[row * 64 + ((lc4 * 4) ^ ZS(row))] = vpre[it];
            }
            if (c < 30) {
#pragma unroll
                for (int it = 0; it < 8; it++) {
                    int row = kc + 128 + lrow + it * 8;
                    kpre[it] = *(const float4*)(Kg + (size_t)row * 64 + lc4 * 4);
                    vpre[it] = *(const float4*)(Vg + (size_t)row * 64 + lc4 * 4);
                }
            }
        }
        __syncthreads();   // P^T + next K/V visible

        // ---- O += P V over kv=64 (f32x2), 8 rows x 4 cols ----
#pragma unroll 8
        for (int k = 0; k < 64; k++) {
            int zk = ZS(k);
            float4 a0 = *(const float4*)&Ps[k * 64 + ((ty * 8) ^ zk)];
            float4 a1 = *(const float4*)&Ps[k * 64 + ((ty * 8 + 4) ^ zk)];
            float4 b  = *(const float4*)&Vb[k * 64 + ((tx * 4) ^ zk)];
            u64t b0 = pk2(b.x, b.y), b1 = pk2(b.z, b.w);
            u64t d0 = pkdup(a0.x), d1 = pkdup(a0.y), d2 = pkdup(a0.z), d3 = pkdup(a0.w);
            u64t d4 = pkdup(a1.x), d5 = pkdup(a1.y), d6 = pkdup(a1.z), d7 = pkdup(a1.w);
            fma2(o2[0][0], d0, b0); fma2(o2[0][1], d0, b1);
            fma2(o2[1][0], d1, b0); fma2(o2[1][1], d1, b1);
            fma2(o2[2][0], d2, b0); fma2(o2[2][1], d2, b1);
            fma2(o2[3][0], d3, b0); fma2(o2[3][1], d3, b1);
            fma2(o2[4][0], d4, b0); fma2(o2[4][1], d4, b1);
            fma2(o2[5][0], d5, b0); fma2(o2[5][1], d5, b1);
            fma2(o2[6][0], d6, b0); fma2(o2[6][1], d6, b1);
            fma2(o2[7][0], d7, b0); fma2(o2[7][1], d7, b1);
        }
        __syncthreads();   // PV reads of Ps/Vb done before next iter overwrites
    }

    // ---- final row-sum reduction (once), normalize, write pre-Wo activations ----
#pragma unroll
    for (int i = 0; i < 8; i++) {
        s_run[i] += __shfl_xor_sync(0xffffffffu, s_run[i], 1);
        s_run[i] += __shfl_xor_sync(0xffffffffu, s_run[i], 2);
        s_run[i] += __shfl_xor_sync(0xffffffffu, s_run[i], 4);
        s_run[i] += __shfl_xor_sync(0xffffffffu, s_run[i], 8);
    }
    const int b_ = bh >> 4, h = bh & 15;
#pragma unroll
    for (int i = 0; i < 8; i++) {
        float inv = 1.0f / s_run[i];
        int m = m0 + ty * 8 + i;
        float2 u0 = upk(o2[i][0]);
        float2 u1 = upk(o2[i][1]);
        *(float4*)(g_attn + (size_t)(b_ * Ss + m) * 1024 + h * 64 + tx * 4) =
            make_float4(u0.x * inv, u0.y * inv, u1.x * inv, u1.y * inv);
    }
}

// ---------------- output projection: pipelined 2-stage GEMM, f32x2 core ----------------
// grid: (8, 64), block 256
__global__ __launch_bounds__(256, 2) void oproj_kernel(const float* __restrict__ Wo,
                                                       const float* __restrict__ bo,
                                                       float* __restrict__ out)
{
    __shared__ float As[2][16][128];
    __shared__ float Bs[2][16][128];
    const int m0 = blockIdx.y * 128, n0 = blockIdx.x * 128;
    const int t = threadIdx.x;
    const int lr = t >> 2, lc = (t & 3) << 2;
    const int ty = t >> 4, tx = t & 15;

    const float* Ar0 = g_attn + (size_t)(m0 + lr) * 1024 + lc;
    const float* Ar1 = Ar0 + (size_t)64 * 1024;
    const float* Br0 = Wo + (size_t)(n0 + lr) * 1024 + lc;
    const float* Br1 = Br0 + (size_t)64 * 1024;

    u64t acc2[8][4];
#pragma unroll
    for (int i = 0; i < 8; i++)
#pragma unroll
        for (int jp = 0; jp < 4; jp++) acc2[i][jp] = 0ull;

    float4 pa0 = *(const float4*)Ar0;
    float4 pa1 = *(const float4*)Ar1;
    float4 pb0 = *(const float4*)Br0;
    float4 pb1 = *(const float4*)Br1;

    for (int tile = 0; tile < 64; tile++) {
        const int cur = tile & 1;
        As[cur][lc + 0][lr] = pa0.x; As[cur][lc + 1][lr] = pa0.y;
        As[cur][lc + 2][lr] = pa0.z; As[cur][lc + 3][lr] = pa0.w;
        As[cur][lc + 0][lr + 64] = pa1.x; As[cur][lc + 1][lr + 64] = pa1.y;
        As[cur][lc + 2][lr + 64] = pa1.z; As[cur][lc + 3][lr + 64] = pa1.w;
        Bs[cur][lc + 0][lr] = pb0.x; Bs[cur][lc + 1][lr] = pb0.y;
        Bs[cur][lc + 2][lr] = pb0.z; Bs[cur][lc + 3][lr] = pb0.w;
        Bs[cur][lc + 0][lr + 64] = pb1.x; Bs[cur][lc + 1][lr + 64] = pb1.y;
        Bs[cur][lc + 2][lr + 64] = pb1.z; Bs[cur][lc + 3][lr + 64] = pb1.w;
        __syncthreads();
        if (tile < 63) {
            int off = (tile + 1) * 16;
            pa0 = *(const float4*)(Ar0 + off);
            pa1 = *(const float4*)(Ar1 + off);
            pb0 = *(const float4*)(Br0 + off);
            pb1 = *(const float4*)(Br1 + off);
        }
#pragma unroll
        for (int k = 0; k < 16; k++) {
            float a[8];
            float4 bl0 = *(const float4*)&Bs[cur][k][tx * 4];
            float4 bl1 = *(const float4*)&Bs[cur][k][tx * 4 + 64];
            *(float4*)(a)     = *(const float4*)&As[cur][k][ty * 4];
            *(float4*)(a + 4) = *(const float4*)&As[cur][k][ty * 4 + 64];
            u64t b2[4];
            b2[0] = pk2(bl0.x, bl0.y); b2[1] = pk2(bl0.z, bl0.w);
            b2[2] = pk2(bl1.x, bl1.y); b2[3] = pk2(bl1.z, bl1.w);
#pragma unroll
            for (int i = 0; i < 8; i++) {
                u64t ai = pkdup(a[i]);
                fma2(acc2[i][0], ai, b2[0]);
                fma2(acc2[i][1], ai, b2[1]);
                fma2(acc2[i][2], ai, b2[2]);
                fma2(acc2[i][3], ai, b2[3]);
            }
        }
    }

#pragma unroll
    for (int i = 0; i < 8; i++) {
        int m = m0 + ty * 4 + (i & 3) + ((i >> 2) << 6);
        float* orow = out + (size_t)m * 1024;
#pragma unroll
        for (int jg = 0; jg < 2; jg++) {
            int n = n0 + tx * 4 + jg * 64;
            float4 bv = *(const float4*)(bo + n);
            float2 u0 = upk(acc2[i][jg * 2 + 0]);
            float2 u1 = upk(acc2[i][jg * 2 + 1]);
            float4 ov;
            ov.x = u0.x + bv.x;
            ov.y = u0.y + bv.y;
            ov.z = u1.x + bv.z;
            ov.w = u1.y + bv.w;
            *(float4*)(orow + n) = ov;
        }
    }
}

// ---------------- launch ----------------
extern "C" void kernel_launch(void* const* d_in, const int* in_sizes, int n_in,
                              void* d_out, int out_size)
{
    const float* x        = (const float*)d_in[0];
    const float* Wq       = (const float*)d_in[1];
    const float* bq       = (const float*)d_in[2];
    const float* Wk       = (const float*)d_in[3];
    const float* Wv       = (const float*)d_in[4];
    const float* bv       = (const float*)d_in[5];
    const float* Wo       = (const float*)d_in[6];
    const float* bo       = (const float*)d_in[7];
    const float* inv_freq = (const float*)d_in[8];
    const float* rbias    = (const float*)d_in[9];
    const float* mask     = (const float*)d_in[10];

    float* out    = (float*)d_out;
    float* qk_out = out + (size_t)BSn * Dd;   // second output: (B,H,S,S)

    // raise dynamic smem limit for the attention kernel (idempotent; host-side, not captured)
    static int smem_set = 0;
    if (!smem_set) {
        cudaFuncSetAttribute(attn_fused_kernel,
                             cudaFuncAttributeMaxDynamicSharedMemorySize, 96 * 1024);
        smem_set = 1;
    }

    rope_table_kernel<<<(Ss * 32 + 255) / 256, 256>>>(inv_freq, rbias);

    dim3 gA(8, 64, 3);
    qkv_kernel<<<gA, 256>>>(x, Wq, bq, Wk, Wv, bv);

    attn_fused_kernel<<<2048, 128, 96 * 1024>>>(mask, qk_out);

    dim3 gD(8, 64);
    oproj_kernel<<<gD, 256>>>(Wo, bo, out);
}